// round 4
// baseline (speedup 1.0000x reference)
#include <cuda_runtime.h>
#include <cuda_fp16.h>

#define TAGSETN 64
#define SEQN    512
#define NTAGS   66
#define STARTS  64
#define STOPS   65
#define LOG2E_F 1.4426950408889634f
#define LN2_F   0.6931471805599453f
#define OFFB    8.0f

__device__ __forceinline__ float ex2f(float x) {
    float r; asm("ex2.approx.ftz.f32 %0, %1;" : "=f"(r) : "f"(x)); return r;
}
__device__ __forceinline__ float lg2f(float x) {
    float r; asm("lg2.approx.ftz.f32 %0, %1;" : "=f"(r) : "f"(x)); return r;
}

// dot over 64 states: broadcast LDS.128 of sa, per-thread E column (32 half2)
__device__ __forceinline__ float dot64(const __half* sa, const __half2* E2) {
    const uint4* p = (const uint4*)sa;
    const __half2 z = __floats2half2_rn(0.f, 0.f);
    __half2 c0 = z, c1 = z, c2 = z, c3 = z;
    #pragma unroll
    for (int q = 0; q < 8; ++q) {
        const uint4 u = p[q];
        c0 = __hfma2(*(const __half2*)&u.x, E2[4*q+0], c0);
        c1 = __hfma2(*(const __half2*)&u.y, E2[4*q+1], c1);
        c2 = __hfma2(*(const __half2*)&u.z, E2[4*q+2], c2);
        c3 = __hfma2(*(const __half2*)&u.w, E2[4*q+3], c3);
    }
    const float2 f = __half22float2(__hadd2(__hadd2(c0, c1), __hadd2(c2, c3)));
    return f.x + f.y;
}

__global__ __launch_bounds__(64, 6)
void crf_fwd_kernel(const float* __restrict__ em,
                    const int*   __restrict__ tags,
                    const float* __restrict__ trans,
                    float*       __restrict__ out)
{
    const int j    = threadIdx.x;        // state 0..63
    const int lane = j & 31;
    const int warp = j >> 5;
    const int bA   = 2 * blockIdx.x;
    const int bB   = 2 * blockIdx.x + 1;

    __shared__ __align__(16) __half saA[TAGSETN], saB[TAGSETN];
    __shared__ float sMA, sMB;
    __shared__ float wred[4];
    __shared__ float wsum[4];
    __shared__ int   wcnt[4];
    __shared__ int   stA[SEQN], stB[SEQN];

    const float* emA = em + (size_t)bA * (SEQN * TAGSETN);
    const float* emB = em + (size_t)bB * (SEQN * TAGSETN);

    #pragma unroll
    for (int q = 0; q < SEQN / 64; ++q) {
        stA[j + 64*q] = tags[bA * SEQN + j + 64*q];
        stB[j + 64*q] = tags[bB * SEQN + j + 64*q];
    }

    // E column j: E2[r] = (exp(T[2r][j]), exp(T[2r+1][j]))
    __half2 E2[32];
    #pragma unroll
    for (int r = 0; r < 32; ++r)
        E2[r] = __floats2half2_rn(__expf(trans[(2*r  )*NTAGS + j]),
                                  __expf(trans[(2*r+1)*NTAGS + j]));

    const float Tst_j  = trans[STARTS * NTAGS + j];
    const float Tend_j = trans[j * NTAGS + STOPS];
    if (j == 0) { wred[2] = Tst_j; wred[3] = Tend_j; }
    __syncthreads();
    const float Tst0  = wred[2];
    const float Tend0 = wred[3];
    const float dTb   = (Tend_j - Tend0) * LOG2E_F;   // 0 for this T
    const float Cuni  = Tst0 + (float)(SEQN - 1) * Tend0;

    // base-2 shifted log-alphas
    float lbA = (emA[j] + Tst_j - Tst0) * LOG2E_F;
    float lbB = (emB[j] + Tst_j - Tst0) * LOG2E_F;

    // exact initial maxima for both batches
    float mA = lbA, mB = lbB;
    #pragma unroll
    for (int o = 16; o; o >>= 1) {
        mA = fmaxf(mA, __shfl_xor_sync(0xffffffffu, mA, o));
        mB = fmaxf(mB, __shfl_xor_sync(0xffffffffu, mB, o));
    }
    if (lane == 0) { wred[warp] = mA; wred[2 + warp] = mB; }
    __syncthreads();
    float MA = fmaxf(wred[0], wred[1]);          // shift for A step 1 (register)
    const float MB0 = fmaxf(wred[2], wred[3]);
    float MB;                                    // loaded in P1

    // prologue: A's sa for step 1; B's shift slot
    saA[j] = __float2half_rn(ex2f(lbA - MA));
    if (j == 0) sMB = MB0;

    // emission prefetch (distance 3) + tag prefetch
    float eA_c = emA[1*TAGSETN + j], eA_1 = emA[2*TAGSETN + j], eA_2 = emA[3*TAGSETN + j];
    float eB_c = emB[1*TAGSETN + j], eB_1 = emB[2*TAGSETN + j], eB_2 = emB[3*TAGSETN + j];
    int tgA = stA[1], tgB = stB[1];
    __syncthreads();                              // covers saA, sMB, stags

    for (int t = 1; t < SEQN; ++t) {
        // ---------- P1: A consumes (step t), B produces (step t) ----------
        MB = sMB;                                 // B's shift (written prev P2)
        const float aB = ex2f(lbB - MB);
        const float sA = dot64(saA, E2);
        saB[j] = __float2half_rn(aB);

        const float scA = fmaf(eA_c, LOG2E_F, MA) + lg2f(sA);
        const bool  mkA = (tgA != 0);
        lbA = (mkA ? scA : lbA) + dTb;
        if (j == 0) sMA = mkA ? (scA + OFFB) : MA;

        eA_c = eA_1; eA_1 = eA_2;
        {
            const int tn = (t + 3 < SEQN) ? (t + 3) : (SEQN - 1);
            eA_2 = emA[tn * TAGSETN + j];
            tgA  = stA[(t + 1 < SEQN) ? (t + 1) : (SEQN - 1)];
        }
        __syncthreads();                          // BAR1

        // ---------- P2: B consumes (step t), A produces (step t+1) ----------
        MA = sMA;                                 // A's shift for step t+1
        const float aA = ex2f(lbA - MA);
        const float sB = dot64(saB, E2);
        saA[j] = __float2half_rn(aA);

        const float scB = fmaf(eB_c, LOG2E_F, MB) + lg2f(sB);
        const bool  mkB = (tgB != 0);
        lbB = (mkB ? scB : lbB) + dTb;
        if (j == 0) sMB = mkB ? (scB + OFFB) : MB;

        eB_c = eB_1; eB_1 = eB_2;
        {
            const int tn = (t + 3 < SEQN) ? (t + 3) : (SEQN - 1);
            eB_2 = emB[tn * TAGSETN + j];
            tgB  = stB[(t + 1 < SEQN) ? (t + 1) : (SEQN - 1)];
        }
        __syncthreads();                          // BAR2
    }

    // ---- final exact logsumexp for both batches ----
    float mzA = lbA, mzB = lbB;
    #pragma unroll
    for (int o = 16; o; o >>= 1) {
        mzA = fmaxf(mzA, __shfl_xor_sync(0xffffffffu, mzA, o));
        mzB = fmaxf(mzB, __shfl_xor_sync(0xffffffffu, mzB, o));
    }
    if (lane == 0) { wred[warp] = mzA; wred[2 + warp] = mzB; }
    __syncthreads();
    const float MzA = fmaxf(wred[0], wred[1]);
    const float MzB = fmaxf(wred[2], wred[3]);
    float azA = ex2f(lbA - MzA);
    float azB = ex2f(lbB - MzB);
    #pragma unroll
    for (int o = 16; o; o >>= 1) {
        azA += __shfl_xor_sync(0xffffffffu, azA, o);
        azB += __shfl_xor_sync(0xffffffffu, azB, o);
    }
    if (lane == 0) { wsum[warp] = azA; wsum[2 + warp] = azB; }
    __syncthreads();
    const float logzA = Cuni + (MzA + lg2f(wsum[0] + wsum[1])) * LN2_F;
    const float logzB = Cuni + (MzB + lg2f(wsum[2] + wsum[3])) * LN2_F;
    __syncthreads();

    // ---- numerators (gold-path scores), both batches ----
    float accA = 0.f, accB = 0.f;
    int   cntA = 0,   cntB = 0;
    #pragma unroll
    for (int q = 0; q < SEQN / 64; ++q) {
        const int t  = j + 64 * q;
        const int a  = stA[t];
        const int bb = stB[t];
        cntA += (a  != 0) ? 1 : 0;
        cntB += (bb != 0) ? 1 : 0;
        if (t == 0) {
            accA += trans[STARTS * NTAGS + a];
            if (a  != 0) accA += emA[a];
            accB += trans[STARTS * NTAGS + bb];
            if (bb != 0) accB += emB[bb];
        } else {
            if (a  != 0) accA += emA[t * TAGSETN + a]  + trans[stA[t-1] * NTAGS + a];
            if (bb != 0) accB += emB[t * TAGSETN + bb] + trans[stB[t-1] * NTAGS + bb];
        }
    }
    #pragma unroll
    for (int o = 16; o; o >>= 1) {
        accA += __shfl_xor_sync(0xffffffffu, accA, o);
        accB += __shfl_xor_sync(0xffffffffu, accB, o);
        cntA += __shfl_xor_sync(0xffffffffu, cntA, o);
        cntB += __shfl_xor_sync(0xffffffffu, cntB, o);
    }
    if (lane == 0) { wsum[warp] = accA; wsum[2+warp] = accB; wcnt[warp] = cntA; wcnt[2+warp] = cntB; }
    __syncthreads();

    if (j == 0) {
        const float aT = wsum[0] + wsum[1];
        int lastA = (wcnt[0] + wcnt[1]) - 1; if (lastA < 0) lastA = 0;
        out[bA] = aT + trans[stA[lastA] * NTAGS + STOPS] - logzA;
    } else if (j == 1) {
        const float bT = wsum[2] + wsum[3];
        int lastB = (wcnt[2] + wcnt[3]) - 1; if (lastB < 0) lastB = 0;
        out[bB] = bT + trans[stB[lastB] * NTAGS + STOPS] - logzB;
    }
}

extern "C" void kernel_launch(void* const* d_in, const int* in_sizes, int n_in,
                              void* d_out, int out_size)
{
    const float* emissions   = (const float*)d_in[0];
    const int*   tags        = (const int*)d_in[1];
    const float* transitions = (const float*)d_in[2];
    float*       out         = (float*)d_out;

    const int B = in_sizes[1] / SEQN;
    crf_fwd_kernel<<<B / 2, 64>>>(emissions, tags, transitions, out);
}

// round 5
// speedup vs baseline: 1.5898x; 1.5898x over previous
#include <cuda_runtime.h>
#include <cuda_fp16.h>

#define TAGSETN 64
#define SEQN    512
#define NTAGS   66
#define STARTS  64
#define STOPS   65
#define LOG2E_F 1.4426950408889634f
#define LN2_F   0.6931471805599453f
#define OFFB    12.0f              // lag-1 shift headroom (base-2)

__device__ __forceinline__ float ex2f(float x) {
    float r; asm("ex2.approx.ftz.f32 %0, %1;" : "=f"(r) : "f"(x)); return r;
}
__device__ __forceinline__ float lg2f(float x) {
    float r; asm("lg2.approx.ftz.f32 %0, %1;" : "=f"(r) : "f"(x)); return r;
}

__global__ __launch_bounds__(64, 8)
void crf_fwd_kernel(const float* __restrict__ em,
                    const int*   __restrict__ tags,
                    const float* __restrict__ trans,
                    float*       __restrict__ out)
{
    const int b    = blockIdx.x;
    const int j    = threadIdx.x;    // state 0..63
    const int lane = j & 31;
    const int warp = j >> 5;

    __shared__ __align__(16) __half sa[2][TAGSETN];  // double-buffered exp(lb-M)
    __shared__ float sM[2];                          // double-buffered shift
    __shared__ float wred[2], wsum[2];
    __shared__ int   wcnt[2];
    __shared__ int   stags[SEQN];

    const float* emb = em + (size_t)b * (SEQN * TAGSETN);
    const int*   tgb = tags + b * SEQN;

    #pragma unroll
    for (int q = 0; q < SEQN / 64; ++q)
        stags[j + 64 * q] = tgb[j + 64 * q];

    // E column j: E2[r] = (exp(T[2r][j]), exp(T[2r+1][j]))
    __half2 E2[32];
    #pragma unroll
    for (int r = 0; r < 32; ++r)
        E2[r] = __floats2half2_rn(__expf(trans[(2*r  )*NTAGS + j]),
                                  __expf(trans[(2*r+1)*NTAGS + j]));

    const float Tst_j  = trans[STARTS * NTAGS + j];
    const float Tend_j = trans[j * NTAGS + STOPS];
    if (j == 0) { wred[0] = Tst_j; wred[1] = Tend_j; }
    __syncthreads();
    const float Tst0  = wred[0];
    const float Tend0 = wred[1];
    const float dTb   = (Tend_j - Tend0) * LOG2E_F;           // 0 for this T
    const float Cuni  = Tst0 + (float)(SEQN - 1) * Tend0;     // exact uniform part

    // base-2 shifted log-alpha (stays O(few thousand); fp32 ulp ~2e-4, fine)
    float lb = (emb[j] + Tst_j - Tst0) * LOG2E_F;

    // exact initial max -> M_0
    float m0 = lb;
    #pragma unroll
    for (int o = 16; o; o >>= 1)
        m0 = fmaxf(m0, __shfl_xor_sync(0xffffffffu, m0, o));
    if (lane == 0) wred[warp] = m0;
    __syncthreads();
    float Mprev = fmaxf(wred[0], wred[1]);   // shift used to build a for step 1

    float a = ex2f(lb - Mprev);              // a_1

    // emission / tag prefetch (distance 3)
    float e_c = emb[1*TAGSETN + j], e_1 = emb[2*TAGSETN + j], e_2 = emb[3*TAGSETN + j];
    int tg_c = stags[1];
    __syncthreads();                         // wred done before loop

    const __half2 h2z = __floats2half2_rn(0.f, 0.f);

    for (int t = 1; t < SEQN; ++t) {
        __half* buf = sa[t & 1];
        buf[j] = __float2half_rn(a);
        if (j == 0) sM[t & 1] = lb + OFFB;   // M_t = lb0(t-1) + OFFB
        __syncthreads();                     // single barrier per step

        const float Mt = sM[t & 1];

        // dot(a, E[:,j]) — broadcast LDS.128, 4 half2 accumulators
        const uint4* p = (const uint4*)buf;
        __half2 c0 = h2z, c1 = h2z, c2 = h2z, c3 = h2z;
        #pragma unroll
        for (int q = 0; q < 8; ++q) {
            const uint4 u = p[q];
            c0 = __hfma2(*(const __half2*)&u.x, E2[4*q+0], c0);
            c1 = __hfma2(*(const __half2*)&u.y, E2[4*q+1], c1);
            c2 = __hfma2(*(const __half2*)&u.z, E2[4*q+2], c2);
            c3 = __hfma2(*(const __half2*)&u.w, E2[4*q+3], c3);
        }
        const float2 f = __half22float2(__hadd2(__hadd2(c0, c1), __hadd2(c2, c3)));
        const float  s = f.x + f.y;

        // a_t was built with shift Mprev = M_{t-1}
        const float score = fmaf(e_c, LOG2E_F, Mprev) + lg2f(s);
        const bool  mk    = (tg_c != 0);
        lb = (mk ? score : lb) + dTb;

        a = ex2f(lb - Mt);                   // a_{t+1}, lag-1 shift
        Mprev = Mt;

        // rotate prefetch
        e_c = e_1; e_1 = e_2;
        const int tn = (t + 3 < SEQN) ? (t + 3) : (SEQN - 1);
        e_2 = emb[tn * TAGSETN + j];
        tg_c = stags[(t + 1 < SEQN) ? (t + 1) : (SEQN - 1)];
    }

    // ---- final exact logsumexp -> log_z ----
    float mz = lb;
    #pragma unroll
    for (int o = 16; o; o >>= 1)
        mz = fmaxf(mz, __shfl_xor_sync(0xffffffffu, mz, o));
    if (lane == 0) wred[warp] = mz;
    __syncthreads();
    const float Mz = fmaxf(wred[0], wred[1]);
    float az = ex2f(lb - Mz);
    #pragma unroll
    for (int o = 16; o; o >>= 1)
        az += __shfl_xor_sync(0xffffffffu, az, o);
    if (lane == 0) wsum[warp] = az;
    __syncthreads();
    const float log_z = Cuni + (Mz + lg2f(wsum[0] + wsum[1])) * LN2_F;
    __syncthreads();

    // ---- numerator (gold-path score) ----
    float acc = 0.f;
    int   cnt = 0;
    #pragma unroll
    for (int q = 0; q < SEQN / 64; ++q) {
        const int t  = j + 64 * q;
        const int tg = stags[t];
        const bool mk = (tg != 0);
        cnt += mk ? 1 : 0;
        if (t == 0) {
            acc += trans[STARTS * NTAGS + tg];
            if (mk) acc += emb[tg];
        } else if (mk) {
            acc += emb[t * TAGSETN + tg] + trans[stags[t-1] * NTAGS + tg];
        }
    }
    #pragma unroll
    for (int o = 16; o; o >>= 1) {
        acc += __shfl_xor_sync(0xffffffffu, acc, o);
        cnt += __shfl_xor_sync(0xffffffffu, cnt, o);
    }
    if (lane == 0) { wsum[warp] = acc; wcnt[warp] = cnt; }
    __syncthreads();

    if (j == 0) {
        const float accT = wsum[0] + wsum[1];
        int last = (wcnt[0] + wcnt[1]) - 1;
        if (last < 0) last = 0;
        out[b] = accT + trans[stags[last] * NTAGS + STOPS] - log_z;
    }
}

extern "C" void kernel_launch(void* const* d_in, const int* in_sizes, int n_in,
                              void* d_out, int out_size)
{
    const float* emissions   = (const float*)d_in[0];
    const int*   tags        = (const int*)d_in[1];
    const float* transitions = (const float*)d_in[2];
    float*       out         = (float*)d_out;

    const int B = in_sizes[1] / SEQN;
    crf_fwd_kernel<<<B, 64>>>(emissions, tags, transitions, out);
}

// round 6
// speedup vs baseline: 1.6031x; 1.0083x over previous
#include <cuda_runtime.h>
#include <cuda_fp16.h>

#define TAGSETN 64
#define SEQN    512
#define NTAGS   66
#define STARTS  64
#define STOPS   65
#define LOG2E_F 1.4426950408889634f
#define LN2_F   0.6931471805599453f
#define OFFB    12.0f              // lag-1 shift headroom (base-2)

__device__ __forceinline__ float ex2f(float x) {
    float r; asm("ex2.approx.ftz.f32 %0, %1;" : "=f"(r) : "f"(x)); return r;
}
__device__ __forceinline__ float lg2f(float x) {
    float r; asm("lg2.approx.ftz.f32 %0, %1;" : "=f"(r) : "f"(x)); return r;
}

__global__ __launch_bounds__(64, 8)
void crf_fwd_kernel(const float* __restrict__ em,
                    const int*   __restrict__ tags,
                    const float* __restrict__ trans,
                    float*       __restrict__ out)
{
    const int b    = blockIdx.x;
    const int j    = threadIdx.x;    // state 0..63
    const int lane = j & 31;
    const int warp = j >> 5;

    __shared__ __align__(16) __half sa[2][TAGSETN];  // double-buffered exp(lb-M)
    __shared__ float sM[2];                          // double-buffered shift
    __shared__ float wred[2], wsum[2];
    __shared__ int   wcnt[2];
    __shared__ int   stags[SEQN];

    const float* emb = em + (size_t)b * (SEQN * TAGSETN);
    const int*   tgb = tags + b * SEQN;

    #pragma unroll
    for (int q = 0; q < SEQN / 64; ++q)
        stags[j + 64 * q] = tgb[j + 64 * q];

    // E column j: E2[r] = (exp(T[2r][j]), exp(T[2r+1][j]))
    __half2 E2[32];
    #pragma unroll
    for (int r = 0; r < 32; ++r)
        E2[r] = __floats2half2_rn(__expf(trans[(2*r  )*NTAGS + j]),
                                  __expf(trans[(2*r+1)*NTAGS + j]));

    const float Tst_j  = trans[STARTS * NTAGS + j];
    const float Tend_j = trans[j * NTAGS + STOPS];
    if (j == 0) { wred[0] = Tst_j; wred[1] = Tend_j; }
    __syncthreads();
    const float Tst0  = wred[0];
    const float Tend0 = wred[1];
    const float dTb   = (Tend_j - Tend0) * LOG2E_F;           // identically 0 here
    const float Cuni  = Tst0 + (float)(SEQN - 1) * Tend0;

    // base-2 shifted log-alpha (only thread 0's copy drives the shift chain)
    float lb = (emb[j] + Tst_j - Tst0) * LOG2E_F;

    // exact initial max -> M_0
    float m0 = lb;
    #pragma unroll
    for (int o = 16; o; o >>= 1)
        m0 = fmaxf(m0, __shfl_xor_sync(0xffffffffu, m0, o));
    if (lane == 0) wred[warp] = m0;
    __syncthreads();
    float Mprev = fmaxf(wred[0], wred[1]);   // shift that built current a

    float a = ex2f(lb - Mprev);              // a_1 (fp32 working copy)

    // emission / tag prefetch (distance 3)
    float e_c = emb[1*TAGSETN + j], e_1 = emb[2*TAGSETN + j], e_2 = emb[3*TAGSETN + j];
    int tg_c = stags[1];
    __syncthreads();                         // wred done before loop

    const __half2 h2z = __floats2half2_rn(0.f, 0.f);

    for (int t = 1; t < SEQN; ++t) {
        const float emL = e_c * LOG2E_F;
        __half* buf = sa[t & 1];
        buf[j] = __float2half_rn(a);
        if (j == 0) sM[t & 1] = lb + OFFB;   // publish M_t = lb0(t-1) + OFFB
        __syncthreads();                     // single barrier per step

        const float Mt = sM[t & 1];
        const float D  = (Mprev - Mt) + dTb;
        const float g  = ex2f(emL + D);      // off-path, parallel with dot
        const float h  = ex2f(D);

        // dot(a, E[:,j]) — broadcast LDS.128, 4 half2 accumulators
        const uint4* p = (const uint4*)buf;
        __half2 c0 = h2z, c1 = h2z, c2 = h2z, c3 = h2z;
        #pragma unroll
        for (int q = 0; q < 8; ++q) {
            const uint4 u = p[q];
            c0 = __hfma2(*(const __half2*)&u.x, E2[4*q+0], c0);
            c1 = __hfma2(*(const __half2*)&u.y, E2[4*q+1], c1);
            c2 = __hfma2(*(const __half2*)&u.z, E2[4*q+2], c2);
            c3 = __hfma2(*(const __half2*)&u.w, E2[4*q+3], c3);
        }
        const float2 f = __half22float2(__hadd2(__hadd2(c0, c1), __hadd2(c2, c3)));
        const float  s = f.x + f.y;

        const bool mk = (tg_c != 0);
        // linear-domain update: critical path after s is one FMUL + select
        a = mk ? (s * g) : (a * h);

        // shift chain (slack: consumed only by next step's g/h)
        const float score = emL + Mprev + lg2f(s);
        lb = (mk ? score : lb) + dTb;
        Mprev = Mt;

        // rotate prefetch
        e_c = e_1; e_1 = e_2;
        const int tn = (t + 3 < SEQN) ? (t + 3) : (SEQN - 1);
        e_2 = emb[tn * TAGSETN + j];
        tg_c = stags[(t + 1 < SEQN) ? (t + 1) : (SEQN - 1)];
    }

    // recover log-alpha: lb_j = lg2(a_j) + M_last  (a==0 -> -inf, safely ignored)
    const float lbf = lg2f(a) + Mprev;

    // ---- final exact logsumexp -> log_z ----
    float mz = lbf;
    #pragma unroll
    for (int o = 16; o; o >>= 1)
        mz = fmaxf(mz, __shfl_xor_sync(0xffffffffu, mz, o));
    if (lane == 0) wred[warp] = mz;
    __syncthreads();
    const float Mz = fmaxf(wred[0], wred[1]);
    float az = ex2f(lbf - Mz);
    #pragma unroll
    for (int o = 16; o; o >>= 1)
        az += __shfl_xor_sync(0xffffffffu, az, o);
    if (lane == 0) wsum[warp] = az;
    __syncthreads();
    const float log_z = Cuni + (Mz + lg2f(wsum[0] + wsum[1])) * LN2_F;
    __syncthreads();

    // ---- numerator (gold-path score) ----
    float acc = 0.f;
    int   cnt = 0;
    #pragma unroll
    for (int q = 0; q < SEQN / 64; ++q) {
        const int t  = j + 64 * q;
        const int tg = stags[t];
        const bool mk = (tg != 0);
        cnt += mk ? 1 : 0;
        if (t == 0) {
            acc += trans[STARTS * NTAGS + tg];
            if (mk) acc += emb[tg];
        } else if (mk) {
            acc += emb[t * TAGSETN + tg] + trans[stags[t-1] * NTAGS + tg];
        }
    }
    #pragma unroll
    for (int o = 16; o; o >>= 1) {
        acc += __shfl_xor_sync(0xffffffffu, acc, o);
        cnt += __shfl_xor_sync(0xffffffffu, cnt, o);
    }
    if (lane == 0) { wsum[warp] = acc; wcnt[warp] = cnt; }
    __syncthreads();

    if (j == 0) {
        const float accT = wsum[0] + wsum[1];
        int last = (wcnt[0] + wcnt[1]) - 1;
        if (last < 0) last = 0;
        out[b] = accT + trans[stags[last] * NTAGS + STOPS] - log_z;
    }
}

extern "C" void kernel_launch(void* const* d_in, const int* in_sizes, int n_in,
                              void* d_out, int out_size)
{
    const float* emissions   = (const float*)d_in[0];
    const int*   tags        = (const int*)d_in[1];
    const float* transitions = (const float*)d_in[2];
    float*       out         = (float*)d_out;

    const int B = in_sizes[1] / SEQN;
    crf_fwd_kernel<<<B, 64>>>(emissions, tags, transitions, out);
}

// round 7
// speedup vs baseline: 1.7095x; 1.0664x over previous
#include <cuda_runtime.h>
#include <cuda_fp16.h>

#define TAGSETN 64
#define SEQN    512
#define MIDT    256
#define NTAGS   66
#define STARTS  64
#define STOPS   65
#define LOG2E_F 1.4426950408889634f
#define LN2_F   0.6931471805599453f
#define OFFB    12.0f
#define BMAX    1024

__device__ float g_alpha[BMAX * TAGSETN];
__device__ float g_beta [BMAX * TAGSETN];

__device__ __forceinline__ float ex2f(float x) {
    float r; asm("ex2.approx.ftz.f32 %0, %1;" : "=f"(r) : "f"(x)); return r;
}
__device__ __forceinline__ float lg2f(float x) {
    float r; asm("lg2.approx.ftz.f32 %0, %1;" : "=f"(r) : "f"(x)); return r;
}

__device__ __forceinline__ float dot64h(const __half* sa, const __half2* E2) {
    const uint4* p = (const uint4*)sa;
    const __half2 z = __floats2half2_rn(0.f, 0.f);
    __half2 c0 = z, c1 = z, c2 = z, c3 = z;
    #pragma unroll
    for (int q = 0; q < 8; ++q) {
        const uint4 u = p[q];
        c0 = __hfma2(*(const __half2*)&u.x, E2[4*q+0], c0);
        c1 = __hfma2(*(const __half2*)&u.y, E2[4*q+1], c1);
        c2 = __hfma2(*(const __half2*)&u.z, E2[4*q+2], c2);
        c3 = __hfma2(*(const __half2*)&u.w, E2[4*q+3], c3);
    }
    const float2 f = __half22float2(__hadd2(__hadd2(c0, c1), __hadd2(c2, c3)));
    return f.x + f.y;
}

// blockIdx.y == 0: forward half (steps 1..256) -> g_alpha
// blockIdx.y == 1: backward half (steps 511..257) -> g_beta
__global__ __launch_bounds__(64, 10)
void crf_half_kernel(const float* __restrict__ em,
                     const int*   __restrict__ tags,
                     const float* __restrict__ trans)
{
    const int b    = blockIdx.x;
    const int fwd  = (blockIdx.y == 0);
    const int j    = threadIdx.x;
    const int lane = j & 31;
    const int warp = j >> 5;

    __shared__ __align__(16) __half sa[2][TAGSETN];
    __shared__ float sM[2];
    __shared__ float wred[2];
    __shared__ int   stags[260];

    const float* emb = em + (size_t)b * (SEQN * TAGSETN);
    const int*   tgb = tags + b * SEQN;

    __half2 E2[32];

    if (fwd) {
        // tags[0..256]
        #pragma unroll
        for (int q = 0; q < 5; ++q) {
            const int k = j + 64 * q;
            if (k <= MIDT) stags[k] = tgb[k];
        }
        // E column j
        #pragma unroll
        for (int r = 0; r < 32; ++r)
            E2[r] = __floats2half2_rn(__expf(trans[(2*r  )*NTAGS + j]),
                                      __expf(trans[(2*r+1)*NTAGS + j]));

        const float Tst_j = trans[STARTS * NTAGS + j];
        const float Tst0  = __ldg(&trans[STARTS * NTAGS + 0]);

        float lb = (emb[j] + Tst_j - Tst0) * LOG2E_F;

        float m0 = lb;
        #pragma unroll
        for (int o = 16; o; o >>= 1)
            m0 = fmaxf(m0, __shfl_xor_sync(0xffffffffu, m0, o));
        if (lane == 0) wred[warp] = m0;
        __syncthreads();
        float Mprev = fmaxf(wred[0], wred[1]);

        float a = ex2f(lb - Mprev);

        float e_c = emb[1*TAGSETN + j], e_1 = emb[2*TAGSETN + j], e_2 = emb[3*TAGSETN + j];
        int tg_c = stags[1];
        __syncthreads();

        for (int t = 1; t <= MIDT; ++t) {
            const float emL = e_c * LOG2E_F;
            __half* buf = sa[t & 1];
            buf[j] = __float2half_rn(a);
            if (j == 0) sM[t & 1] = lb + OFFB;
            __syncthreads();

            const float Mt = sM[t & 1];
            const float D  = Mprev - Mt;
            const float g  = ex2f(emL + D);
            const float h  = ex2f(D);

            const float s  = dot64h(buf, E2);

            const bool mk = (tg_c != 0);
            a  = mk ? (s * g) : (a * h);
            const float score = emL + Mprev + lg2f(s);
            lb = mk ? score : lb;
            Mprev = Mt;

            e_c = e_1; e_1 = e_2;
            const int tn = (t + 3 <= MIDT) ? (t + 3) : MIDT;
            e_2 = emb[tn * TAGSETN + j];
            tg_c = stags[(t + 1 <= MIDT) ? (t + 1) : MIDT];
        }

        g_alpha[b * TAGSETN + j] = lg2f(a) + Mprev;
    } else {
        // tags[257..511] -> stags[0..254]
        #pragma unroll
        for (int q = 0; q < 4; ++q) {
            const int k = j + 64 * q;
            if (k <= 254) stags[k] = tgb[257 + k];
        }
        // E row j (contiguous)
        #pragma unroll
        for (int r = 0; r < 32; ++r)
            E2[r] = __floats2half2_rn(__expf(trans[j*NTAGS + 2*r    ]),
                                      __expf(trans[j*NTAGS + 2*r + 1]));

        float lb = 0.f;          // beta_511 = 0
        float Mprev = 0.f;
        float a = 1.f;

        float e_c = emb[511*TAGSETN + j], e_1 = emb[510*TAGSETN + j], e_2 = emb[509*TAGSETN + j];
        int tg_c = stags[254];   // tags[511]
        __syncthreads();

        for (int t = 511; t >= 257; --t) {
            const float emL = e_c * LOG2E_F;
            const float u   = a * ex2f(emL);     // emission folded pre-barrier
            __half* buf = sa[t & 1];
            buf[j] = __float2half_rn(u);
            if (j == 0) sM[t & 1] = lb + OFFB;
            __syncthreads();

            const float Mt = sM[t & 1];
            const float h  = ex2f(Mprev - Mt);

            const float s  = dot64h(buf, E2);

            const bool mk = (tg_c != 0);
            a  = (mk ? s : a) * h;
            const float score = Mprev + lg2f(s);
            lb = mk ? score : lb;
            Mprev = Mt;

            e_c = e_1; e_1 = e_2;
            const int tn = (t - 3 >= 257) ? (t - 3) : 257;
            e_2 = emb[tn * TAGSETN + j];
            const int tp = (t - 1 >= 257) ? (t - 1) : 257;
            tg_c = stags[tp - 257];
        }

        g_beta[b * TAGSETN + j] = lg2f(a) + Mprev;
    }
}

__global__ __launch_bounds__(64)
void crf_combine_kernel(const float* __restrict__ em,
                        const int*   __restrict__ tags,
                        const float* __restrict__ trans,
                        float*       __restrict__ out)
{
    const int b    = blockIdx.x;
    const int j    = threadIdx.x;
    const int lane = j & 31;
    const int warp = j >> 5;

    __shared__ float wred[2], wsum[2];
    __shared__ int   wcnt[2];
    __shared__ int   stags[SEQN];

    const float* emb = em + (size_t)b * (SEQN * TAGSETN);
    const int*   tgb = tags + b * SEQN;

    #pragma unroll
    for (int q = 0; q < SEQN / 64; ++q)
        stags[j + 64 * q] = tgb[j + 64 * q];

    const float Tst0  = __ldg(&trans[STARTS * NTAGS + 0]);
    const float Tend0 = __ldg(&trans[0 * NTAGS + STOPS]);
    const float Cuni  = Tst0 + (float)(SEQN - 1) * Tend0;

    const float v = g_alpha[b * TAGSETN + j] + g_beta[b * TAGSETN + j];

    float mz = v;
    #pragma unroll
    for (int o = 16; o; o >>= 1)
        mz = fmaxf(mz, __shfl_xor_sync(0xffffffffu, mz, o));
    if (lane == 0) wred[warp] = mz;
    __syncthreads();
    const float Mz = fmaxf(wred[0], wred[1]);
    float az = ex2f(v - Mz);
    #pragma unroll
    for (int o = 16; o; o >>= 1)
        az += __shfl_xor_sync(0xffffffffu, az, o);
    if (lane == 0) wsum[warp] = az;
    __syncthreads();
    const float log_z = Cuni + (Mz + lg2f(wsum[0] + wsum[1])) * LN2_F;
    __syncthreads();

    // numerator (gold-path score)
    float acc = 0.f;
    int   cnt = 0;
    #pragma unroll
    for (int q = 0; q < SEQN / 64; ++q) {
        const int t  = j + 64 * q;
        const int tg = stags[t];
        const bool mk = (tg != 0);
        cnt += mk ? 1 : 0;
        if (t == 0) {
            acc += trans[STARTS * NTAGS + tg];
            if (mk) acc += emb[tg];
        } else if (mk) {
            acc += emb[t * TAGSETN + tg] + trans[stags[t-1] * NTAGS + tg];
        }
    }
    #pragma unroll
    for (int o = 16; o; o >>= 1) {
        acc += __shfl_xor_sync(0xffffffffu, acc, o);
        cnt += __shfl_xor_sync(0xffffffffu, cnt, o);
    }
    if (lane == 0) { wsum[warp] = acc; wcnt[warp] = cnt; }
    __syncthreads();

    if (j == 0) {
        const float accT = wsum[0] + wsum[1];
        int last = (wcnt[0] + wcnt[1]) - 1;
        if (last < 0) last = 0;
        out[b] = accT + trans[stags[last] * NTAGS + STOPS] - log_z;
    }
}

extern "C" void kernel_launch(void* const* d_in, const int* in_sizes, int n_in,
                              void* d_out, int out_size)
{
    const float* emissions   = (const float*)d_in[0];
    const int*   tags        = (const int*)d_in[1];
    const float* transitions = (const float*)d_in[2];
    float*       out         = (float*)d_out;

    const int B = in_sizes[1] / SEQN;

    dim3 grid(B, 2);
    crf_half_kernel<<<grid, 64>>>(emissions, tags, transitions);
    crf_combine_kernel<<<B, 64>>>(emissions, tags, transitions, out);
}

// round 8
// speedup vs baseline: 1.9350x; 1.1319x over previous
#include <cuda_runtime.h>
#include <cuda_fp16.h>

#define TAGSETN 64
#define SEQN    512
#define MIDT    256
#define NTAGS   66
#define STARTS  64
#define STOPS   65
#define LOG2E_F 1.4426950408889634f
#define LN2_F   0.6931471805599453f
#define OFFB    12.0f

#define BARS(id) asm volatile("bar.sync %0, %1;" :: "r"(id), "r"(64) : "memory")

__device__ __forceinline__ float ex2f(float x) {
    float r; asm("ex2.approx.ftz.f32 %0, %1;" : "=f"(r) : "f"(x)); return r;
}
__device__ __forceinline__ float lg2f(float x) {
    float r; asm("lg2.approx.ftz.f32 %0, %1;" : "=f"(r) : "f"(x)); return r;
}

__device__ __forceinline__ float dot64h(const __half* sa, const __half2* E2) {
    const uint4* p = (const uint4*)sa;
    const __half2 z = __floats2half2_rn(0.f, 0.f);
    __half2 c0 = z, c1 = z, c2 = z, c3 = z;
    #pragma unroll
    for (int q = 0; q < 8; ++q) {
        const uint4 u = p[q];
        c0 = __hfma2(*(const __half2*)&u.x, E2[4*q+0], c0);
        c1 = __hfma2(*(const __half2*)&u.y, E2[4*q+1], c1);
        c2 = __hfma2(*(const __half2*)&u.z, E2[4*q+2], c2);
        c3 = __hfma2(*(const __half2*)&u.w, E2[4*q+3], c3);
    }
    const float2 f = __half22float2(__hadd2(__hadd2(c0, c1), __hadd2(c2, c3)));
    return f.x + f.y;
}

__global__ __launch_bounds__(128, 7)
void crf_fused_kernel(const float* __restrict__ em,
                      const int*   __restrict__ tags,
                      const float* __restrict__ trans,
                      float*       __restrict__ out)
{
    const int b    = blockIdx.x;
    const int tid  = threadIdx.x;
    const int half = tid >> 6;          // 0 = forward, 1 = backward
    const int j    = tid & 63;          // state index within half
    const int lane = tid & 31;
    const int wh   = (tid >> 5) & 1;    // warp within half (0/1)

    __shared__ __align__(16) __half saF[2][TAGSETN], saB[2][TAGSETN];
    __shared__ float sMF[2], sMB[2];
    __shared__ float wredF[2];
    __shared__ float zred[2], zsum[2];
    __shared__ float nsum[2];
    __shared__ int   ncnt[2];
    __shared__ float sAlpha[TAGSETN], sBeta[TAGSETN];
    __shared__ int   stags[SEQN];

    const float* emb = em + (size_t)b * (SEQN * TAGSETN);
    const int*   tgb = tags + b * SEQN;

    #pragma unroll
    for (int q = 0; q < SEQN / 128; ++q)
        stags[tid + 128 * q] = tgb[tid + 128 * q];
    __syncthreads();

    __half2 E2[32];

    if (half == 0) {
        // ---------------- forward: alpha_0 .. alpha_256 ----------------
        #pragma unroll
        for (int r = 0; r < 32; ++r)
            E2[r] = __floats2half2_rn(__expf(trans[(2*r  )*NTAGS + j]),
                                      __expf(trans[(2*r+1)*NTAGS + j]));

        const float Tst_j = trans[STARTS * NTAGS + j];
        const float Tst0  = __ldg(&trans[STARTS * NTAGS + 0]);

        float lb = (emb[j] + Tst_j - Tst0) * LOG2E_F;

        float m0 = lb;
        #pragma unroll
        for (int o = 16; o; o >>= 1)
            m0 = fmaxf(m0, __shfl_xor_sync(0xffffffffu, m0, o));
        if (lane == 0) wredF[wh] = m0;
        BARS(1);
        float Mprev = fmaxf(wredF[0], wredF[1]);

        float a = ex2f(lb - Mprev);

        float e_c = emb[1*TAGSETN + j], e_1 = emb[2*TAGSETN + j], e_2 = emb[3*TAGSETN + j];
        int tg_c = stags[1];
        BARS(1);

        for (int t = 1; t <= MIDT; ++t) {
            const float emL = e_c * LOG2E_F;
            __half* buf = saF[t & 1];
            buf[j] = __float2half_rn(a);
            if (j == 0) sMF[t & 1] = lb + OFFB;
            BARS(1);

            const float Mt = sMF[t & 1];
            const float D  = Mprev - Mt;
            const float g  = ex2f(emL + D);
            const float h  = ex2f(D);

            const float s  = dot64h(buf, E2);

            const bool mk = (tg_c != 0);
            a  = mk ? (s * g) : (a * h);
            lb = mk ? (emL + Mprev + lg2f(s)) : lb;
            Mprev = Mt;

            e_c = e_1; e_1 = e_2;
            const int tn = (t + 3 <= MIDT) ? (t + 3) : MIDT;
            e_2 = emb[tn * TAGSETN + j];
            tg_c = stags[(t + 1 <= MIDT) ? (t + 1) : MIDT];
        }

        sAlpha[j] = lg2f(a) + Mprev;
    } else {
        // ---------------- backward: beta_511 .. beta_256 ----------------
        #pragma unroll
        for (int r = 0; r < 32; ++r)
            E2[r] = __floats2half2_rn(__expf(trans[j*NTAGS + 2*r    ]),
                                      __expf(trans[j*NTAGS + 2*r + 1]));

        float lb = 0.f, Mprev = 0.f, a = 1.f;

        float e_c = emb[511*TAGSETN + j], e_1 = emb[510*TAGSETN + j], e_2 = emb[509*TAGSETN + j];
        int tg_c = stags[511];

        for (int t = 511; t >= 257; --t) {
            const float emL = e_c * LOG2E_F;
            const float u   = a * ex2f(emL);       // fold emission pre-barrier
            __half* buf = saB[t & 1];
            buf[j] = __float2half_rn(u);
            if (j == 0) sMB[t & 1] = lb + OFFB;
            BARS(2);

            const float Mt = sMB[t & 1];
            const float h  = ex2f(Mprev - Mt);

            const float s  = dot64h(buf, E2);

            const bool mk = (tg_c != 0);
            a  = (mk ? s : a) * h;
            lb = mk ? (Mprev + lg2f(s)) : lb;
            Mprev = Mt;

            e_c = e_1; e_1 = e_2;
            const int tn = (t - 3 >= 257) ? (t - 3) : 257;
            e_2 = emb[tn * TAGSETN + j];
            const int tp = (t - 1 >= 257) ? (t - 1) : 257;
            tg_c = stags[tp];
        }

        sBeta[j] = lg2f(a) + Mprev;
    }

    __syncthreads();

    // ---------------- combine (both halves work concurrently) ----------------
    if (half == 0) {
        // log_z = Cuni + lse(alpha + beta)
        const float v = sAlpha[j] + sBeta[j];
        float mz = v;
        #pragma unroll
        for (int o = 16; o; o >>= 1)
            mz = fmaxf(mz, __shfl_xor_sync(0xffffffffu, mz, o));
        if (lane == 0) zred[wh] = mz;
        BARS(1);
        const float Mz = fmaxf(zred[0], zred[1]);
        float az = ex2f(v - Mz);
        #pragma unroll
        for (int o = 16; o; o >>= 1)
            az += __shfl_xor_sync(0xffffffffu, az, o);
        if (lane == 0) zsum[wh] = az;
    } else {
        // numerator (gold-path score); emissions rows are L2-hot
        float acc = 0.f;
        int   cnt = 0;
        #pragma unroll
        for (int q = 0; q < SEQN / 64; ++q) {
            const int t  = j + 64 * q;
            const int tg = stags[t];
            const bool mk = (tg != 0);
            cnt += mk ? 1 : 0;
            if (t == 0) {
                acc += trans[STARTS * NTAGS + tg];
                if (mk) acc += emb[tg];
            } else if (mk) {
                acc += emb[t * TAGSETN + tg] + trans[stags[t-1] * NTAGS + tg];
            }
        }
        #pragma unroll
        for (int o = 16; o; o >>= 1) {
            acc += __shfl_xor_sync(0xffffffffu, acc, o);
            cnt += __shfl_xor_sync(0xffffffffu, cnt, o);
        }
        if (lane == 0) { nsum[wh] = acc; ncnt[wh] = cnt; }
    }

    __syncthreads();

    if (tid == 0) {
        const float Tst0  = __ldg(&trans[STARTS * NTAGS + 0]);
        const float Tend0 = __ldg(&trans[0 * NTAGS + STOPS]);
        const float Cuni  = Tst0 + (float)(SEQN - 1) * Tend0;
        const float log_z = Cuni + (fmaxf(zred[0], zred[1])
                            + lg2f(zsum[0] + zsum[1])) * LN2_F;
        const float accT  = nsum[0] + nsum[1];
        int last = (ncnt[0] + ncnt[1]) - 1;
        if (last < 0) last = 0;
        out[b] = accT + trans[stags[last] * NTAGS + STOPS] - log_z;
    }
}

extern "C" void kernel_launch(void* const* d_in, const int* in_sizes, int n_in,
                              void* d_out, int out_size)
{
    const float* emissions   = (const float*)d_in[0];
    const int*   tags        = (const int*)d_in[1];
    const float* transitions = (const float*)d_in[2];
    float*       out         = (float*)d_out;

    const int B = in_sizes[1] / SEQN;
    crf_fused_kernel<<<B, 128>>>(emissions, tags, transitions, out);
}